// round 2
// baseline (speedup 1.0000x reference)
#include <cuda_runtime.h>
#include <cstdint>

// Binarize: x[4096, 8192] fp32, depth[3] -> out[4096, 3, 1024] (packed bytes,
// harness dtype = float32: each output element is the numeric value of the
// big-endian packed byte).
//
// Thread owns 32 consecutive floats (8x float4 loads), emits 4 bytes per
// depth plane as one float4 store per plane (coalesced).

#define COLS 8192
#define BPR  (COLS / 8)    // 1024 bytes (floats) per row per depth plane
#define TPR  256           // threads per row: each covers 32 elements

__global__ __launch_bounds__(256) void binarize_kernel(
    const float* __restrict__ x,
    const float* __restrict__ depth,
    float* __restrict__ out)
{
    const int tid = blockIdx.x * blockDim.x + threadIdx.x;
    const int b = tid >> 8;        // row
    const int t = tid & 255;       // 32-element chunk within the row

    const float d0 = __ldg(depth + 0);
    const float d1 = __ldg(depth + 1);
    const float d2 = __ldg(depth + 2);

    const float4* p = reinterpret_cast<const float4*>(
        x + (size_t)b * COLS + (size_t)t * 32);

    // Front-batch all 8 vector loads (MLP=8) to hide DRAM latency.
    float4 v[8];
#pragma unroll
    for (int k = 0; k < 8; k++) v[k] = p[k];

    // bytes[plane][c] accumulates the big-endian packed byte for elements 8c..8c+7
    uint32_t by[3][4];
#pragma unroll
    for (int pl = 0; pl < 3; pl++)
#pragma unroll
        for (int c = 0; c < 4; c++) by[pl][c] = 0u;

#pragma unroll
    for (int k = 0; k < 8; k++) {
        const float f[4] = { v[k].x, v[k].y, v[k].z, v[k].w };
#pragma unroll
        for (int j = 0; j < 4; j++) {
            const int e     = k * 4 + j;       // element index 0..31 (constant)
            const int c     = e >> 3;          // byte index 0..3
            const uint32_t w = 1u << (7 - (e & 7)); // big-endian bit weight
            by[0][c] |= (f[j] > d0) ? w : 0u;
            by[1][c] |= (f[j] > d1) ? w : 0u;
            by[2][c] |= (f[j] > d2) ? w : 0u;
        }
    }

    // out is [B, 3, BPR] float32. Thread t writes float4 slot t of each plane.
    float4* o = reinterpret_cast<float4*>(out + (size_t)b * 3 * BPR) + t;
#pragma unroll
    for (int pl = 0; pl < 3; pl++) {
        float4 r;
        r.x = (float)by[pl][0];
        r.y = (float)by[pl][1];
        r.z = (float)by[pl][2];
        r.w = (float)by[pl][3];
        o[(size_t)pl * (BPR / 4)] = r;
    }
}

extern "C" void kernel_launch(void* const* d_in, const int* in_sizes, int n_in,
                              void* d_out, int out_size) {
    const float* x     = (const float*)d_in[0];
    const float* depth = (const float*)d_in[1];
    float*       out   = (float*)d_out;

    const int n = in_sizes[0];               // 4096 * 8192
    const int total_threads = n / 32;        // one thread per 32 floats
    const int block = 256;
    const int grid  = total_threads / block; // 4096

    binarize_kernel<<<grid, block>>>(x, depth, out);
}

// round 3
// speedup vs baseline: 1.1894x; 1.1894x over previous
#include <cuda_runtime.h>
#include <cstdint>

// Binarize: x[4096, 8192] fp32, depth[3] -> out[4096, 3, 1024] float32,
// each output element = numeric value of the big-endian packed byte.
//
// R3: fix L1-wavefront bottleneck. Each thread owns 8 CONSECUTIVE floats
// (2x LDG.128, lane stride 32B -> 8 lines per load wavefront-group instead
// of 32 with the old 128B stride), producing exactly one byte per depth
// plane (3x coalesced STG.32, one 128B line per warp per plane).
// Persistent grid-stride loop, streaming cache hints.

#define COLS 8192
#define BPR  (COLS / 8)     // 1024 packed bytes (output floats) per row per plane

__global__ __launch_bounds__(256) void binarize_kernel(
    const float* __restrict__ x,
    const float* __restrict__ depth,
    float* __restrict__ out,
    int nchunks)            // total 8-element chunks = n/8
{
    const float d0 = __ldg(depth + 0);
    const float d1 = __ldg(depth + 1);
    const float d2 = __ldg(depth + 2);

    const float4* __restrict__ x4 = reinterpret_cast<const float4*>(x);

    const int stride = gridDim.x * blockDim.x;
    for (int c = blockIdx.x * blockDim.x + threadIdx.x; c < nchunks; c += stride) {
        // 8 consecutive floats: float4 indices 2c, 2c+1 (consecutive threads ->
        // consecutive 32B lane regions, coalesced).
        const float4 a = __ldcs(x4 + 2 * (size_t)c);
        const float4 b = __ldcs(x4 + 2 * (size_t)c + 1);

        // Big-endian packbits: element e (0..7) has weight 1 << (7-e).
        uint32_t m0 = 0, m1 = 0, m2 = 0;
        const float f[8] = { a.x, a.y, a.z, a.w, b.x, b.y, b.z, b.w };
#pragma unroll
        for (int e = 0; e < 8; e++) {
            const uint32_t w = 1u << (7 - e);
            m0 |= (f[e] > d0) ? w : 0u;
            m1 |= (f[e] > d1) ? w : 0u;
            m2 |= (f[e] > d2) ? w : 0u;
        }

        // c is the global byte index: row = c / 1024, byte-in-row = c % 1024.
        const int row = c >> 10;
        const int t   = c & (BPR - 1);
        float* o = out + (size_t)row * (3 * BPR) + t;
        __stcs(o,            (float)m0);
        __stcs(o + BPR,      (float)m1);
        __stcs(o + 2 * BPR,  (float)m2);
    }
}

extern "C" void kernel_launch(void* const* d_in, const int* in_sizes, int n_in,
                              void* d_out, int out_size) {
    const float* x     = (const float*)d_in[0];
    const float* depth = (const float*)d_in[1];
    float*       out   = (float*)d_out;

    const int n       = in_sizes[0];   // 4096 * 8192
    const int nchunks = n / 8;         // one byte (8 elements) per thread-iter

    const int block = 256;
    int grid = 148 * 8;                // persistent: 8 blocks/SM
    const int max_grid = (nchunks + block - 1) / block;
    if (grid > max_grid) grid = max_grid;

    binarize_kernel<<<grid, block>>>(x, depth, out, nchunks);
}